// round 12
// baseline (speedup 1.0000x reference)
#include <cuda_runtime.h>
#include <float.h>

// NormmaxBisect, alpha = 1.5, n_iter = 50, d = 2048.
// p = max(x - tau, 0)^2 ; p^alpha = max(x - tau, 0)^3.
// Only elements with x > max-1 can be nonzero. Output = zero-fill + scatter.
// tau* via Newton on f(tau) = sum c^3 - 1 (convex, decreasing; started on the
// f>=0 side => monotone quadratic convergence, warp-uniform early exit);
// lands within ~1 ulp of the reference's 50-step fp32 bisection.
//
// WARP-AUTONOMOUS: one warp owns one row end-to-end. No shared memory, no
// __syncthreads, no idle warps, no cross-warp serialization. Pass 1 streams
// the row (max + zero-fill); pass 2 re-reads it (L2-hot: 8KB/warp, ~10MB
// resident) gathering candidates into 4 regs/lane; Newton + scatter per warp.

constexpr int   D       = 2048;
constexpr int   THREADS = 256;
constexpr int   WPB     = THREADS / 32;               // 8 rows per block
constexpr int   EPL4    = D / 4 / 32;                 // 16 float4 per lane
constexpr float TAU_HI_OFF = 0.022097086912079612f;   // (1/2048)^0.5

__global__ void __launch_bounds__(THREADS)
normmax_kernel(const float* __restrict__ X, float* __restrict__ Out, int nrows)
{
    const int lane = threadIdx.x & 31;
    const int row  = blockIdx.x * WPB + (threadIdx.x >> 5);
    if (row >= nrows) return;

    const size_t base = (size_t)row * D;
    const float4* __restrict__ xin  = reinterpret_cast<const float4*>(X + base);
    float4* __restrict__       xout = reinterpret_cast<float4*>(Out + base);
    const float4 z4 = make_float4(0.f, 0.f, 0.f, 0.f);

    // ---- Pass 1: stream row, zero-fill output, running max ----
    float m = -FLT_MAX;
#pragma unroll 4
    for (int k = 0; k < EPL4; ++k) {
        float4 v = xin[lane + 32 * k];
        xout[lane + 32 * k] = z4;
        m = fmaxf(m, fmaxf(fmaxf(v.x, v.y), fmaxf(v.z, v.w)));
    }
#pragma unroll
    for (int o = 16; o; o >>= 1)
        m = fmaxf(m, __shfl_xor_sync(0xffffffffu, m, o));

    const float thresh = m - 1.0f;
    const float tau_hi = m - TAU_HI_OFF;      // f(tau_hi) < 0 always

    // Order this warp's zero-fill before its scatter (in-warp memory sync).
    __syncwarp();

    // ---- Pass 2: re-read (L2-hot), gather candidates into 4 regs/lane ----
    const float SENT = -1.0e30f;              // contributes exactly 0 via fmaxf
    float cv0 = SENT, cv1 = SENT, cv2 = SENT, cv3 = SENT;
    int   p0 = 0, p1 = 0, p2 = 0, p3 = 0;
    int   cnt = 0;
#pragma unroll 4
    for (int k = 0; k < EPL4; ++k) {
        float4 v = xin[lane + 32 * k];
        const int e = 4 * (lane + 32 * k);
        if (v.x > thresh) { cv0 = (cnt == 0) ? v.x : cv0; p0 = (cnt == 0) ? e   : p0;
                            cv1 = (cnt == 1) ? v.x : cv1; p1 = (cnt == 1) ? e   : p1;
                            cv2 = (cnt == 2) ? v.x : cv2; p2 = (cnt == 2) ? e   : p2;
                            cv3 = (cnt == 3) ? v.x : cv3; p3 = (cnt == 3) ? e   : p3; ++cnt; }
        if (v.y > thresh) { cv0 = (cnt == 0) ? v.y : cv0; p0 = (cnt == 0) ? e+1 : p0;
                            cv1 = (cnt == 1) ? v.y : cv1; p1 = (cnt == 1) ? e+1 : p1;
                            cv2 = (cnt == 2) ? v.y : cv2; p2 = (cnt == 2) ? e+1 : p2;
                            cv3 = (cnt == 3) ? v.y : cv3; p3 = (cnt == 3) ? e+1 : p3; ++cnt; }
        if (v.z > thresh) { cv0 = (cnt == 0) ? v.z : cv0; p0 = (cnt == 0) ? e+2 : p0;
                            cv1 = (cnt == 1) ? v.z : cv1; p1 = (cnt == 1) ? e+2 : p1;
                            cv2 = (cnt == 2) ? v.z : cv2; p2 = (cnt == 2) ? e+2 : p2;
                            cv3 = (cnt == 3) ? v.z : cv3; p3 = (cnt == 3) ? e+2 : p3; ++cnt; }
        if (v.w > thresh) { cv0 = (cnt == 0) ? v.w : cv0; p0 = (cnt == 0) ? e+3 : p0;
                            cv1 = (cnt == 1) ? v.w : cv1; p1 = (cnt == 1) ? e+3 : p1;
                            cv2 = (cnt == 2) ? v.w : cv2; p2 = (cnt == 2) ? e+3 : p2;
                            cv3 = (cnt == 3) ? v.w : cv3; p3 = (cnt == 3) ? e+3 : p3; ++cnt; }
    }

    // Per-lane capacity 4; overflow is ~1e-5 per lane -> exact dense fallback.
    const unsigned of = __ballot_sync(0xffffffffu, cnt > 4);

    if (of == 0) {
        // ---- Newton on f(tau) = sum c^3 - 1, candidates in registers ----
        float tau = thresh;                   // f(thresh) >= 0
#pragma unroll 1
        for (int it = 0; it < 8; ++it) {
            float c0 = fmaxf(cv0 - tau, 0.f), q0 = c0 * c0;
            float c1 = fmaxf(cv1 - tau, 0.f), q1 = c1 * c1;
            float c2 = fmaxf(cv2 - tau, 0.f), q2 = c2 * c2;
            float c3 = fmaxf(cv3 - tau, 0.f), q3 = c3 * c3;
            float a = (q0 + q1) + (q2 + q3);                              // sum c^2
            float b = fmaf(q0, c0, fmaf(q1, c1, fmaf(q2, c2, q3 * c3))); // sum c^3
#pragma unroll
            for (int o = 16; o; o >>= 1) {    // two independent chains pipeline
                a += __shfl_xor_sync(0xffffffffu, a, o);
                b += __shfl_xor_sync(0xffffffffu, b, o);
            }
            // f = b - 1, f' = -3a  (a >= (m-tau)^2 > 0 while tau <= tau_hi)
            float nt = tau + (b - 1.0f) / (3.0f * a);
            nt = fminf(fmaxf(nt, thresh), tau_hi);
            if (nt == tau) break;             // converged (warp-uniform: a,b
            tau = nt;                         // bit-identical on all lanes)
        }

        // ---- Final S = sum c^2 and scatter ----
        float c0 = fmaxf(cv0 - tau, 0.f), q0 = c0 * c0;
        float c1 = fmaxf(cv1 - tau, 0.f), q1 = c1 * c1;
        float c2 = fmaxf(cv2 - tau, 0.f), q2 = c2 * c2;
        float c3 = fmaxf(cv3 - tau, 0.f), q3 = c3 * c3;
        float S = (q0 + q1) + (q2 + q3);
#pragma unroll
        for (int o = 16; o; o >>= 1) S += __shfl_xor_sync(0xffffffffu, S, o);
        const float invS = 1.0f / S;

        // q == 0 (SENT slots or clamped candidates) -> stays zero-filled.
        if (q0 > 0.f) Out[base + p0] = q0 * invS;
        if (q1 > 0.f) Out[base + p1] = q1 * invS;
        if (q2 > 0.f) Out[base + p2] = q2 * invS;
        if (q3 > 0.f) Out[base + p3] = q3 * invS;
    } else {
        // ---- Dense fallback (~1e-5 of rows): exact reference bisection,
        //      whole warp, row re-read through L2. Writes every element. ----
        float tau_lo = thresh;
        float dm     = tau_hi - tau_lo;
        float tau_m  = tau_lo;
        for (int it = 0; it < 50; ++it) {
            dm *= 0.5f;
            tau_m = tau_lo + dm;
            if (tau_m == tau_lo) break;
            float s = 0.f;
            for (int j = lane; j < D; j += 32) {
                float c = fmaxf(X[base + j] - tau_m, 0.f);
                s = fmaf(c * c, c, s);
            }
#pragma unroll
            for (int o = 16; o; o >>= 1) s += __shfl_xor_sync(0xffffffffu, s, o);
            if (s >= 1.0f) tau_lo = tau_m;
        }
        float S = 0.f;
        for (int j = lane; j < D; j += 32) {
            float c = fmaxf(X[base + j] - tau_m, 0.f);
            S = fmaf(c, c, S);
        }
#pragma unroll
        for (int o = 16; o; o >>= 1) S += __shfl_xor_sync(0xffffffffu, S, o);
        const float invS = 1.0f / S;
        for (int j = lane; j < D; j += 32) {
            float c = fmaxf(X[base + j] - tau_m, 0.f);
            Out[base + j] = c * c * invS;
        }
    }
}

extern "C" void kernel_launch(void* const* d_in, const int* in_sizes, int n_in,
                              void* d_out, int out_size) {
    const float* X = (const float*)d_in[0];
    float* Out = (float*)d_out;
    int nrows = out_size / D;
    int nblocks = (nrows + WPB - 1) / WPB;
    normmax_kernel<<<nblocks, THREADS>>>(X, Out, nrows);
}